// round 14
// baseline (speedup 1.0000x reference)
#include <cuda_runtime.h>
#include <cstdint>
#include <math.h>

#define B_  4
#define S_  2048
#define D_  1024
#define H_  16
#define DH_ 64
#define MROWS (B_ * S_)
#define VPAD 68

typedef unsigned long long ull;

__device__ __forceinline__ ull pk2(float a, float b) {
    ull r; asm("mov.b64 %0, {%1, %2};" : "=l"(r) : "f"(a), "f"(b)); return r;
}
__device__ __forceinline__ float2 up2(ull v) {
    float2 r; asm("mov.b64 {%0, %1}, %2;" : "=f"(r.x), "=f"(r.y) : "l"(v)); return r;
}
__device__ __forceinline__ ull f2fma(ull a, ull b, ull c) {
    ull d; asm("fma.rn.f32x2 %0, %1, %2, %3;" : "=l"(d) : "l"(a), "l"(b), "l"(c)); return d;
}
__device__ __forceinline__ ull f2mul(ull a, ull b) {
    ull d; asm("mul.rn.f32x2 %0, %1, %2;" : "=l"(d) : "l"(a), "l"(b)); return d;
}
__device__ __forceinline__ float ex2(float x) {
    float y; asm("ex2.approx.f32 %0, %1;" : "=f"(y) : "f"(x)); return y;
}
__device__ __forceinline__ void cpasync16(uint32_t smem, const void* gptr) {
    asm volatile("cp.async.ca.shared.global [%0], [%1], 16;"
                 :: "r"(smem), "l"(gptr) : "memory");
}
__device__ __forceinline__ uint32_t s2u(const void* p) {
    uint32_t a;
    asm("{ .reg .u64 t; cvta.to.shared.u64 t, %1; cvt.u32.u64 %0, t; }"
        : "=r"(a) : "l"(p));
    return a;
}

__device__ float g_q[MROWS * D_];
__device__ float g_k[MROWS * D_];
__device__ float g_v[MROWS * D_];
__device__ float g_o[MROWS * D_];

// ---------------------------------------------------------------------------
// GEMM v4 (unchanged — 66% fma, ~76% of f32x2 roof).
// ---------------------------------------------------------------------------
__global__ __launch_bounds__(256, 2) void gemm128(
    const float* __restrict__ A0, const float* __restrict__ A1, const float* __restrict__ A2,
    const float* __restrict__ W0, const float* __restrict__ W1, const float* __restrict__ W2,
    float* __restrict__ C0, float* __restrict__ C1, float* __restrict__ C2)
{
    const float* A; const float* W; float* C;
    if (blockIdx.z == 0)      { A = A0; W = W0; C = C0; }
    else if (blockIdx.z == 1) { A = A1; W = W1; C = C1; }
    else                      { A = A2; W = W2; C = C2; }

    __shared__ __align__(16) float As[2][16][128];
    __shared__ __align__(16) float Bs[2][16][128];

    const int tid = threadIdx.x;
    const int m0  = (tid >> 5) << 4;
    const int n0  = (tid & 31) << 2;
    const size_t mBase = (size_t)blockIdx.y * 128;
    const size_t nBase = (size_t)blockIdx.x * 128;

    const int lrow = tid >> 1;
    const int lkq  = (tid & 1) << 3;

    const float* aG = A + (mBase + lrow) * D_ + lkq;
    const float* wG = W + (nBase + lrow) * D_ + lkq;

    float4 pa0 = *(const float4*)aG, pa1 = *(const float4*)(aG + 4);
    float4 pb0 = *(const float4*)wG, pb1 = *(const float4*)(wG + 4);

    ull acc[8][4];
#pragma unroll
    for (int i = 0; i < 8; i++)
#pragma unroll
        for (int j = 0; j < 4; j++) acc[i][j] = 0ULL;

#define STORE_STAGE(s)                                                        \
    {                                                                         \
        As[s][lkq + 0][lrow] = pa0.x;  As[s][lkq + 1][lrow] = pa0.y;          \
        As[s][lkq + 2][lrow] = pa0.z;  As[s][lkq + 3][lrow] = pa0.w;          \
        As[s][lkq + 4][lrow] = pa1.x;  As[s][lkq + 5][lrow] = pa1.y;          \
        As[s][lkq + 6][lrow] = pa1.z;  As[s][lkq + 7][lrow] = pa1.w;          \
        Bs[s][lkq + 0][lrow] = pb0.x;  Bs[s][lkq + 1][lrow] = pb0.y;          \
        Bs[s][lkq + 2][lrow] = pb0.z;  Bs[s][lkq + 3][lrow] = pb0.w;          \
        Bs[s][lkq + 4][lrow] = pb1.x;  Bs[s][lkq + 5][lrow] = pb1.y;          \
        Bs[s][lkq + 6][lrow] = pb1.z;  Bs[s][lkq + 7][lrow] = pb1.w;          \
    }

    STORE_STAGE(0);
    aG += 16; wG += 16;
    pa0 = *(const float4*)aG;  pa1 = *(const float4*)(aG + 4);
    pb0 = *(const float4*)wG;  pb1 = *(const float4*)(wG + 4);
    __syncthreads();

    const int NT = D_ / 16;
    for (int t = 0; t < NT; t++) {
        const int cur = t & 1;
#pragma unroll
        for (int k = 0; k < 16; k++) {
            ulonglong2 a01 = *(const ulonglong2*)&As[cur][k][m0];
            ulonglong2 a23 = *(const ulonglong2*)&As[cur][k][m0 + 4];
            ulonglong2 a45 = *(const ulonglong2*)&As[cur][k][m0 + 8];
            ulonglong2 a67 = *(const ulonglong2*)&As[cur][k][m0 + 12];
            float4 bv = *(const float4*)&Bs[cur][k][n0];
            ull b0 = pk2(bv.x, bv.x), b1 = pk2(bv.y, bv.y);
            ull b2 = pk2(bv.z, bv.z), b3 = pk2(bv.w, bv.w);
            acc[0][0] = f2fma(a01.x, b0, acc[0][0]);
            acc[0][1] = f2fma(a01.x, b1, acc[0][1]);
            acc[0][2] = f2fma(a01.x, b2, acc[0][2]);
            acc[0][3] = f2fma(a01.x, b3, acc[0][3]);
            acc[1][0] = f2fma(a01.y, b0, acc[1][0]);
            acc[1][1] = f2fma(a01.y, b1, acc[1][1]);
            acc[1][2] = f2fma(a01.y, b2, acc[1][2]);
            acc[1][3] = f2fma(a01.y, b3, acc[1][3]);
            acc[2][0] = f2fma(a23.x, b0, acc[2][0]);
            acc[2][1] = f2fma(a23.x, b1, acc[2][1]);
            acc[2][2] = f2fma(a23.x, b2, acc[2][2]);
            acc[2][3] = f2fma(a23.x, b3, acc[2][3]);
            acc[3][0] = f2fma(a23.y, b0, acc[3][0]);
            acc[3][1] = f2fma(a23.y, b1, acc[3][1]);
            acc[3][2] = f2fma(a23.y, b2, acc[3][2]);
            acc[3][3] = f2fma(a23.y, b3, acc[3][3]);
            acc[4][0] = f2fma(a45.x, b0, acc[4][0]);
            acc[4][1] = f2fma(a45.x, b1, acc[4][1]);
            acc[4][2] = f2fma(a45.x, b2, acc[4][2]);
            acc[4][3] = f2fma(a45.x, b3, acc[4][3]);
            acc[5][0] = f2fma(a45.y, b0, acc[5][0]);
            acc[5][1] = f2fma(a45.y, b1, acc[5][1]);
            acc[5][2] = f2fma(a45.y, b2, acc[5][2]);
            acc[5][3] = f2fma(a45.y, b3, acc[5][3]);
            acc[6][0] = f2fma(a67.x, b0, acc[6][0]);
            acc[6][1] = f2fma(a67.x, b1, acc[6][1]);
            acc[6][2] = f2fma(a67.x, b2, acc[6][2]);
            acc[6][3] = f2fma(a67.x, b3, acc[6][3]);
            acc[7][0] = f2fma(a67.y, b0, acc[7][0]);
            acc[7][1] = f2fma(a67.y, b1, acc[7][1]);
            acc[7][2] = f2fma(a67.y, b2, acc[7][2]);
            acc[7][3] = f2fma(a67.y, b3, acc[7][3]);
        }
        if (t < NT - 1) {
            STORE_STAGE(cur ^ 1);
            if (t < NT - 2) {
                aG += 16; wG += 16;
                pa0 = *(const float4*)aG;  pa1 = *(const float4*)(aG + 4);
                pb0 = *(const float4*)wG;  pb1 = *(const float4*)(wG + 4);
            }
        }
        __syncthreads();
    }
#undef STORE_STAGE

#pragma unroll
    for (int p = 0; p < 8; p++) {
        float2 c0 = up2(acc[p][0]), c1 = up2(acc[p][1]);
        float2 c2 = up2(acc[p][2]), c3 = up2(acc[p][3]);
        float* r0 = C + (mBase + m0 + 2 * p) * D_ + nBase + n0;
        *(float4*)r0        = make_float4(c0.x, c1.x, c2.x, c3.x);
        *(float4*)(r0 + D_) = make_float4(c0.y, c1.y, c2.y, c3.y);
    }
}

// ---------------------------------------------------------------------------
// Flash v4: cp.async double-buffered V, slim K reg-prefetch (16 regs),
// one barrier per tile, exp2-domain softmax, shfl PV.
// smem: Qs 32K + Ks[2] 32K + Vs[2] 34K = 98K -> 2 CTA/SM.
// ---------------------------------------------------------------------------
#define LOG2E_SCALE 0.18033688011112042f   // (1/8) * log2(e)

__global__ __launch_bounds__(256, 2) void flash_v4(
    const float* __restrict__ Qp, const float* __restrict__ Kp,
    const float* __restrict__ Vp, float* __restrict__ Op)
{
    extern __shared__ __align__(16) char smr[];
    float* Qs = (float*)smr;                 // [64 d][128 q]
    float* Ks = Qs + 64 * 128;               // [2][64 d][64 k]
    float* Vs = Ks + 2 * 64 * 64;            // [2][64 k][VPAD d]

    const int tid = threadIdx.x;
    const int n0  = (tid & 7) << 3;
    const int m0  = (tid >> 3) << 2;
    const int bx  = gridDim.x - 1 - blockIdx.x;   // heavy blocks first
    const int qBase = bx * 128;
    const int b = blockIdx.y >> 4, h = blockIdx.y & 15;
    const size_t headOff = (size_t)b * S_ * D_ + (size_t)h * DH_;

    const int kr = tid >> 2, dq = (tid & 3) << 4;
    const int nkt = 2 * bx + 2;
    const float* kBase = Kp + headOff + (size_t)kr * D_ + dq;
    const float* vBase = Vp + headOff + (size_t)kr * D_ + dq;
    const uint32_t vsBase = s2u(Vs) + (uint32_t)(kr * VPAD + dq) * 4u;

    {   // Q -> smem d-major, prescaled by (1/8)*log2(e)
        int qr = tid >> 1, dh = (tid & 1) * 32;
        const float* qs = Qp + headOff + (size_t)(qBase + qr) * D_ + dh;
#pragma unroll
        for (int c = 0; c < 8; c++) {
            float4 v = *(const float4*)(qs + 4 * c);
            Qs[(dh + 4*c + 0) * 128 + qr] = v.x * LOG2E_SCALE;
            Qs[(dh + 4*c + 1) * 128 + qr] = v.y * LOG2E_SCALE;
            Qs[(dh + 4*c + 2) * 128 + qr] = v.z * LOG2E_SCALE;
            Qs[(dh + 4*c + 3) * 128 + qr] = v.w * LOG2E_SCALE;
        }
    }

    // prologue: K tile0 -> regs; V tile0 -> smem stage 0 via cp.async
    float4 kv[4];
#pragma unroll
    for (int c = 0; c < 4; c++) kv[c] = *(const float4*)(kBase + 4*c);
#pragma unroll
    for (int c = 0; c < 4; c++) cpasync16(vsBase + 16u*c, vBase + 4*c);
    asm volatile("cp.async.commit_group;" ::: "memory");

    ull o[4][4];
#pragma unroll
    for (int i = 0; i < 4; i++)
#pragma unroll
        for (int j = 0; j < 4; j++) o[i][j] = 0ULL;
    float mrow[4] = {-INFINITY, -INFINITY, -INFINITY, -INFINITY};
    float lrow[4] = {0.f, 0.f, 0.f, 0.f};

    for (int kt = 0; kt < nkt; kt++) {
        const int cur = kt & 1;
        float* KsC = Ks + cur * 64 * 64;
        const float* VsC = Vs + cur * 64 * VPAD;

        asm volatile("cp.async.wait_group 0;" ::: "memory");  // V[cur] landed
        // K[cur] regs -> smem (transposed to d-major)
#pragma unroll
        for (int c = 0; c < 4; c++) {
            KsC[(dq + 4*c + 0) * 64 + kr] = kv[c].x;
            KsC[(dq + 4*c + 1) * 64 + kr] = kv[c].y;
            KsC[(dq + 4*c + 2) * 64 + kr] = kv[c].z;
            KsC[(dq + 4*c + 3) * 64 + kr] = kv[c].w;
        }
        __syncthreads();   // K/V[cur] visible; stage cur^1 free (prev-prev consumed)

        // launch next tile's loads (hidden under this tile's compute)
        if (kt + 1 < nkt) {
            const float* kp = kBase + (size_t)(kt + 1) * 64 * D_;
            const float* vp = vBase + (size_t)(kt + 1) * 64 * D_;
#pragma unroll
            for (int c = 0; c < 4; c++) kv[c] = *(const float4*)(kp + 4*c);
            uint32_t vd = vsBase + (uint32_t)((cur ^ 1) * 64 * VPAD) * 4u;
#pragma unroll
            for (int c = 0; c < 4; c++) cpasync16(vd + 16u*c, vp + 4*c);
        }
        asm volatile("cp.async.commit_group;" ::: "memory");

        // ---- S = Q K^T (log2 domain) ----
        ull s2[4][4];
#pragma unroll
        for (int i = 0; i < 4; i++)
#pragma unroll
            for (int j = 0; j < 4; j++) s2[i][j] = 0ULL;
        for (int d8 = 0; d8 < 8; d8++) {
#pragma unroll
            for (int dd = 0; dd < 8; dd++) {
                const int d = d8 * 8 + dd;
                float4 qv = *(const float4*)&Qs[d * 128 + m0];
                ulonglong2 k01 = *(const ulonglong2*)&KsC[d * 64 + n0];
                ulonglong2 k23 = *(const ulonglong2*)&KsC[d * 64 + n0 + 4];
                float qa[4] = {qv.x, qv.y, qv.z, qv.w};
#pragma unroll
                for (int i = 0; i < 4; i++) {
                    ull q2 = pk2(qa[i], qa[i]);
                    s2[i][0] = f2fma(q2, k01.x, s2[i][0]);
                    s2[i][1] = f2fma(q2, k01.y, s2[i][1]);
                    s2[i][2] = f2fma(q2, k23.x, s2[i][2]);
                    s2[i][3] = f2fma(q2, k23.y, s2[i][3]);
                }
            }
        }

        // ---- online softmax (exp2 domain), stats across 8-lane groups ----
        float sv[4][8];
        const bool bnd = (kt >= nkt - 2);
        const int kOff = kt * 64 + n0;
#pragma unroll
        for (int i = 0; i < 4; i++) {
#pragma unroll
            for (int j2 = 0; j2 < 4; j2++) {
                float2 u = up2(s2[i][j2]);
                sv[i][2*j2] = u.x; sv[i][2*j2+1] = u.y;
            }
            if (bnd) {
                int q = qBase + m0 + i;
#pragma unroll
                for (int j = 0; j < 8; j++)
                    if (kOff + j > q) sv[i][j] = -INFINITY;
            }
            float mx = sv[i][0];
#pragma unroll
            for (int j = 1; j < 8; j++) mx = fmaxf(mx, sv[i][j]);
            mx = fmaxf(mx, __shfl_xor_sync(0xffffffffu, mx, 1, 8));
            mx = fmaxf(mx, __shfl_xor_sync(0xffffffffu, mx, 2, 8));
            mx = fmaxf(mx, __shfl_xor_sync(0xffffffffu, mx, 4, 8));
            float nm = fmaxf(mrow[i], mx);
            float corr = ex2(mrow[i] - nm);
            mrow[i] = nm;
            float ss = 0.f;
#pragma unroll
            for (int j = 0; j < 8; j++) { float p = ex2(sv[i][j] - nm); sv[i][j] = p; ss += p; }
            ss += __shfl_xor_sync(0xffffffffu, ss, 1, 8);
            ss += __shfl_xor_sync(0xffffffffu, ss, 2, 8);
            ss += __shfl_xor_sync(0xffffffffu, ss, 4, 8);
            lrow[i] = lrow[i] * corr + ss;
            ull c2 = pk2(corr, corr);
#pragma unroll
            for (int j = 0; j < 4; j++) o[i][j] = f2mul(o[i][j], c2);
        }

        // ---- O += P V (P broadcast via shfl width 8) ----
        for (int sl = 0; sl < 8; sl++) {
#pragma unroll
            for (int j = 0; j < 8; j++) {
                const int kl = sl * 8 + j;
                ulonglong2 v01 = *(const ulonglong2*)&VsC[kl * VPAD + n0];
                ulonglong2 v23 = *(const ulonglong2*)&VsC[kl * VPAD + n0 + 4];
#pragma unroll
                for (int i = 0; i < 4; i++) {
                    float p = __shfl_sync(0xffffffffu, sv[i][j], sl, 8);
                    ull p2 = pk2(p, p);
                    o[i][0] = f2fma(p2, v01.x, o[i][0]);
                    o[i][1] = f2fma(p2, v01.y, o[i][1]);
                    o[i][2] = f2fma(p2, v23.x, o[i][2]);
                    o[i][3] = f2fma(p2, v23.y, o[i][3]);
                }
            }
        }
        __syncthreads();   // all reads of stage cur done before next overwrite
    }

#pragma unroll
    for (int i = 0; i < 4; i++) {
        float inv = 1.0f / lrow[i];
        ull iv = pk2(inv, inv);
        float2 a = up2(f2mul(o[i][0], iv)), b2 = up2(f2mul(o[i][1], iv));
        float2 c = up2(f2mul(o[i][2], iv)), d2 = up2(f2mul(o[i][3], iv));
        float* op = Op + headOff + (size_t)(qBase + m0 + i) * D_ + n0;
        *(float4*)op       = make_float4(a.x, a.y, b2.x, b2.y);
        *(float4*)(op + 4) = make_float4(c.x, c.y, d2.x, d2.y);
    }
}

// ---------------------------------------------------------------------------
extern "C" void kernel_launch(void* const* d_in, const int* in_sizes, int n_in,
                              void* d_out, int out_size)
{
    const float* Q  = (const float*)d_in[0];
    const float* Kx = (const float*)d_in[1];
    const float* Vx = (const float*)d_in[2];
    const float* Wq = (const float*)d_in[3];
    const float* Wk = (const float*)d_in[4];
    const float* Wv = (const float*)d_in[5];
    const float* Wo = (const float*)d_in[6];
    float* out = (float*)d_out;

    float *q, *k, *v, *o;
    cudaGetSymbolAddress((void**)&q, g_q);
    cudaGetSymbolAddress((void**)&k, g_k);
    cudaGetSymbolAddress((void**)&v, g_v);
    cudaGetSymbolAddress((void**)&o, g_o);

    const int flashSmem =
        (64 * 128 + 2 * 64 * 64 + 2 * 64 * VPAD) * sizeof(float); // 100352
    cudaFuncSetAttribute(flash_v4, cudaFuncAttributeMaxDynamicSharedMemorySize, flashSmem);

    gemm128<<<dim3(8, 64, 3), 256>>>(Q, Kx, Vx, Wq, Wk, Wv, q, k, v);
    flash_v4<<<dim3(S_ / 128, B_ * H_), 256, flashSmem>>>(q, k, v, o);
    gemm128<<<dim3(8, 64, 1), 256>>>(o, o, o, Wo, Wo, Wo, out, out, out);
}

// round 16
// speedup vs baseline: 1.0706x; 1.0706x over previous
#include <cuda_runtime.h>
#include <cstdint>
#include <math.h>

#define B_  4
#define S_  2048
#define D_  1024
#define H_  16
#define DH_ 64
#define MROWS (B_ * S_)
#define VPAD 68
#define PPAD 68

typedef unsigned long long ull;

__device__ __forceinline__ ull pk2(float a, float b) {
    ull r; asm("mov.b64 %0, {%1, %2};" : "=l"(r) : "f"(a), "f"(b)); return r;
}
__device__ __forceinline__ float2 up2(ull v) {
    float2 r; asm("mov.b64 {%0, %1}, %2;" : "=f"(r.x), "=f"(r.y) : "l"(v)); return r;
}
__device__ __forceinline__ ull f2fma(ull a, ull b, ull c) {
    ull d; asm("fma.rn.f32x2 %0, %1, %2, %3;" : "=l"(d) : "l"(a), "l"(b), "l"(c)); return d;
}
__device__ __forceinline__ ull f2mul(ull a, ull b) {
    ull d; asm("mul.rn.f32x2 %0, %1, %2;" : "=l"(d) : "l"(a), "l"(b)); return d;
}
__device__ __forceinline__ float ex2(float x) {
    float y; asm("ex2.approx.f32 %0, %1;" : "=f"(y) : "f"(x)); return y;
}

__device__ float g_q[MROWS * D_];
__device__ float g_k[MROWS * D_];
__device__ float g_v[MROWS * D_];
__device__ float g_o[MROWS * D_];

// ---------------------------------------------------------------------------
// GEMM v4 (unchanged — 66% fma, ~76% of f32x2 roof).
// ---------------------------------------------------------------------------
__global__ __launch_bounds__(256, 2) void gemm128(
    const float* __restrict__ A0, const float* __restrict__ A1, const float* __restrict__ A2,
    const float* __restrict__ W0, const float* __restrict__ W1, const float* __restrict__ W2,
    float* __restrict__ C0, float* __restrict__ C1, float* __restrict__ C2)
{
    const float* A; const float* W; float* C;
    if (blockIdx.z == 0)      { A = A0; W = W0; C = C0; }
    else if (blockIdx.z == 1) { A = A1; W = W1; C = C1; }
    else                      { A = A2; W = W2; C = C2; }

    __shared__ __align__(16) float As[2][16][128];
    __shared__ __align__(16) float Bs[2][16][128];

    const int tid = threadIdx.x;
    const int m0  = (tid >> 5) << 4;
    const int n0  = (tid & 31) << 2;
    const size_t mBase = (size_t)blockIdx.y * 128;
    const size_t nBase = (size_t)blockIdx.x * 128;

    const int lrow = tid >> 1;
    const int lkq  = (tid & 1) << 3;

    const float* aG = A + (mBase + lrow) * D_ + lkq;
    const float* wG = W + (nBase + lrow) * D_ + lkq;

    float4 pa0 = *(const float4*)aG, pa1 = *(const float4*)(aG + 4);
    float4 pb0 = *(const float4*)wG, pb1 = *(const float4*)(wG + 4);

    ull acc[8][4];
#pragma unroll
    for (int i = 0; i < 8; i++)
#pragma unroll
        for (int j = 0; j < 4; j++) acc[i][j] = 0ULL;

#define STORE_STAGE(s)                                                        \
    {                                                                         \
        As[s][lkq + 0][lrow] = pa0.x;  As[s][lkq + 1][lrow] = pa0.y;          \
        As[s][lkq + 2][lrow] = pa0.z;  As[s][lkq + 3][lrow] = pa0.w;          \
        As[s][lkq + 4][lrow] = pa1.x;  As[s][lkq + 5][lrow] = pa1.y;          \
        As[s][lkq + 6][lrow] = pa1.z;  As[s][lkq + 7][lrow] = pa1.w;          \
        Bs[s][lkq + 0][lrow] = pb0.x;  Bs[s][lkq + 1][lrow] = pb0.y;          \
        Bs[s][lkq + 2][lrow] = pb0.z;  Bs[s][lkq + 3][lrow] = pb0.w;          \
        Bs[s][lkq + 4][lrow] = pb1.x;  Bs[s][lkq + 5][lrow] = pb1.y;          \
        Bs[s][lkq + 6][lrow] = pb1.z;  Bs[s][lkq + 7][lrow] = pb1.w;          \
    }

    STORE_STAGE(0);
    aG += 16; wG += 16;
    pa0 = *(const float4*)aG;  pa1 = *(const float4*)(aG + 4);
    pb0 = *(const float4*)wG;  pb1 = *(const float4*)(wG + 4);
    __syncthreads();

    const int NT = D_ / 16;
    for (int t = 0; t < NT; t++) {
        const int cur = t & 1;
#pragma unroll
        for (int k = 0; k < 16; k++) {
            ulonglong2 a01 = *(const ulonglong2*)&As[cur][k][m0];
            ulonglong2 a23 = *(const ulonglong2*)&As[cur][k][m0 + 4];
            ulonglong2 a45 = *(const ulonglong2*)&As[cur][k][m0 + 8];
            ulonglong2 a67 = *(const ulonglong2*)&As[cur][k][m0 + 12];
            float4 bv = *(const float4*)&Bs[cur][k][n0];
            ull b0 = pk2(bv.x, bv.x), b1 = pk2(bv.y, bv.y);
            ull b2 = pk2(bv.z, bv.z), b3 = pk2(bv.w, bv.w);
            acc[0][0] = f2fma(a01.x, b0, acc[0][0]);
            acc[0][1] = f2fma(a01.x, b1, acc[0][1]);
            acc[0][2] = f2fma(a01.x, b2, acc[0][2]);
            acc[0][3] = f2fma(a01.x, b3, acc[0][3]);
            acc[1][0] = f2fma(a01.y, b0, acc[1][0]);
            acc[1][1] = f2fma(a01.y, b1, acc[1][1]);
            acc[1][2] = f2fma(a01.y, b2, acc[1][2]);
            acc[1][3] = f2fma(a01.y, b3, acc[1][3]);
            acc[2][0] = f2fma(a23.x, b0, acc[2][0]);
            acc[2][1] = f2fma(a23.x, b1, acc[2][1]);
            acc[2][2] = f2fma(a23.x, b2, acc[2][2]);
            acc[2][3] = f2fma(a23.x, b3, acc[2][3]);
            acc[3][0] = f2fma(a23.y, b0, acc[3][0]);
            acc[3][1] = f2fma(a23.y, b1, acc[3][1]);
            acc[3][2] = f2fma(a23.y, b2, acc[3][2]);
            acc[3][3] = f2fma(a23.y, b3, acc[3][3]);
            acc[4][0] = f2fma(a45.x, b0, acc[4][0]);
            acc[4][1] = f2fma(a45.x, b1, acc[4][1]);
            acc[4][2] = f2fma(a45.x, b2, acc[4][2]);
            acc[4][3] = f2fma(a45.x, b3, acc[4][3]);
            acc[5][0] = f2fma(a45.y, b0, acc[5][0]);
            acc[5][1] = f2fma(a45.y, b1, acc[5][1]);
            acc[5][2] = f2fma(a45.y, b2, acc[5][2]);
            acc[5][3] = f2fma(a45.y, b3, acc[5][3]);
            acc[6][0] = f2fma(a67.x, b0, acc[6][0]);
            acc[6][1] = f2fma(a67.x, b1, acc[6][1]);
            acc[6][2] = f2fma(a67.x, b2, acc[6][2]);
            acc[6][3] = f2fma(a67.x, b3, acc[6][3]);
            acc[7][0] = f2fma(a67.y, b0, acc[7][0]);
            acc[7][1] = f2fma(a67.y, b1, acc[7][1]);
            acc[7][2] = f2fma(a67.y, b2, acc[7][2]);
            acc[7][3] = f2fma(a67.y, b3, acc[7][3]);
        }
        if (t < NT - 1) {
            STORE_STAGE(cur ^ 1);
            if (t < NT - 2) {
                aG += 16; wG += 16;
                pa0 = *(const float4*)aG;  pa1 = *(const float4*)(aG + 4);
                pb0 = *(const float4*)wG;  pb1 = *(const float4*)(wG + 4);
            }
        }
        __syncthreads();
    }
#undef STORE_STAGE

#pragma unroll
    for (int p = 0; p < 8; p++) {
        float2 c0 = up2(acc[p][0]), c1 = up2(acc[p][1]);
        float2 c2 = up2(acc[p][2]), c3 = up2(acc[p][3]);
        float* r0 = C + (mBase + m0 + 2 * p) * D_ + nBase + n0;
        *(float4*)r0        = make_float4(c0.x, c1.x, c2.x, c3.x);
        *(float4*)(r0 + D_) = make_float4(c0.y, c1.y, c2.y, c3.y);
    }
}

// ---------------------------------------------------------------------------
// Flash v3b: exact R13 structure (best), with exp2-domain softmax.
// smem: Qs 32K + Ks 16K + Vs 17K + Ps 34K = 99.3 KB -> 2 CTA/SM.
// ---------------------------------------------------------------------------
#define LOG2E_SCALE 0.18033688011112042f   // (1/8) * log2(e)

__global__ __launch_bounds__(256, 2) void flash_v3b(
    const float* __restrict__ Qp, const float* __restrict__ Kp,
    const float* __restrict__ Vp, float* __restrict__ Op)
{
    extern __shared__ __align__(16) char smr[];
    float* Qs = (float*)smr;            // [64 d][128 q]
    float* Ks = Qs + 64 * 128;          // [64 d][64 k]
    float* Vs = Ks + 64 * 64;           // [64 k][VPAD d]
    float* Ps = Vs + 64 * VPAD;         // [128 q][PPAD k]

    const int tid = threadIdx.x;
    const int n0  = (tid & 7) << 3;
    const int m0  = (tid >> 3) << 2;
    const int bx  = gridDim.x - 1 - blockIdx.x;   // heavy blocks first
    const int qBase = bx * 128;
    const int b = blockIdx.y >> 4, h = blockIdx.y & 15;
    const size_t headOff = (size_t)b * S_ * D_ + (size_t)h * DH_;

    {   // Q -> smem d-major, prescaled by (1/8)*log2(e)
        int qr = tid >> 1, dh = (tid & 1) * 32;
        const float* qs = Qp + headOff + (size_t)(qBase + qr) * D_ + dh;
#pragma unroll
        for (int c = 0; c < 8; c++) {
            float4 v = *(const float4*)(qs + 4 * c);
            Qs[(dh + 4*c + 0) * 128 + qr] = v.x * LOG2E_SCALE;
            Qs[(dh + 4*c + 1) * 128 + qr] = v.y * LOG2E_SCALE;
            Qs[(dh + 4*c + 2) * 128 + qr] = v.z * LOG2E_SCALE;
            Qs[(dh + 4*c + 3) * 128 + qr] = v.w * LOG2E_SCALE;
        }
    }

    ull o[4][4];
#pragma unroll
    for (int i = 0; i < 4; i++)
#pragma unroll
        for (int j = 0; j < 4; j++) o[i][j] = 0ULL;
    float mrow[4] = {-INFINITY, -INFINITY, -INFINITY, -INFINITY};
    float lrow[4] = {0.f, 0.f, 0.f, 0.f};

    const int kr = tid >> 2, dq = (tid & 3) << 4;
    const int nkt = 2 * bx + 2;
    const float* kBase = Kp + headOff + (size_t)kr * D_ + dq;
    const float* vBase = Vp + headOff + (size_t)kr * D_ + dq;

    // prologue: load tile 0
    float4 kv[4], vv[4];
#pragma unroll
    for (int c = 0; c < 4; c++) {
        kv[c] = *(const float4*)(kBase + 4*c);
        vv[c] = *(const float4*)(vBase + 4*c);
    }

    for (int kt = 0; kt < nkt; kt++) {
        __syncthreads();                 // prev tile fully consumed (incl. Ps)
#pragma unroll
        for (int c = 0; c < 4; c++) {
            Ks[(dq + 4*c + 0) * 64 + kr] = kv[c].x;
            Ks[(dq + 4*c + 1) * 64 + kr] = kv[c].y;
            Ks[(dq + 4*c + 2) * 64 + kr] = kv[c].z;
            Ks[(dq + 4*c + 3) * 64 + kr] = kv[c].w;
            *(float4*)&Vs[kr * VPAD + dq + 4*c] = vv[c];
        }
        __syncthreads();

        // ---- S = Q K^T (log2 domain) ----
        ull s2[4][4];
#pragma unroll
        for (int i = 0; i < 4; i++)
#pragma unroll
            for (int j = 0; j < 4; j++) s2[i][j] = 0ULL;
        for (int d8 = 0; d8 < 8; d8++) {
#pragma unroll
            for (int dd = 0; dd < 8; dd++) {
                const int d = d8 * 8 + dd;
                float4 qv = *(const float4*)&Qs[d * 128 + m0];
                ulonglong2 k01 = *(const ulonglong2*)&Ks[d * 64 + n0];
                ulonglong2 k23 = *(const ulonglong2*)&Ks[d * 64 + n0 + 4];
                float qa[4] = {qv.x, qv.y, qv.z, qv.w};
#pragma unroll
                for (int i = 0; i < 4; i++) {
                    ull q2 = pk2(qa[i], qa[i]);
                    s2[i][0] = f2fma(q2, k01.x, s2[i][0]);
                    s2[i][1] = f2fma(q2, k01.y, s2[i][1]);
                    s2[i][2] = f2fma(q2, k23.x, s2[i][2]);
                    s2[i][3] = f2fma(q2, k23.y, s2[i][3]);
                }
            }
        }

        // ---- online softmax (exp2 domain); write exp'd P to smem ----
        const bool bnd = (kt >= nkt - 2);
        const int kOff = kt * 64 + n0;
#pragma unroll
        for (int i = 0; i < 4; i++) {
            float sv[8];
#pragma unroll
            for (int j2 = 0; j2 < 4; j2++) {
                float2 u = up2(s2[i][j2]);
                sv[2*j2] = u.x; sv[2*j2+1] = u.y;
            }
            if (bnd) {
                int q = qBase + m0 + i;
#pragma unroll
                for (int j = 0; j < 8; j++)
                    if (kOff + j > q) sv[j] = -INFINITY;
            }
            float mx = sv[0];
#pragma unroll
            for (int j = 1; j < 8; j++) mx = fmaxf(mx, sv[j]);
            mx = fmaxf(mx, __shfl_xor_sync(0xffffffffu, mx, 1, 8));
            mx = fmaxf(mx, __shfl_xor_sync(0xffffffffu, mx, 2, 8));
            mx = fmaxf(mx, __shfl_xor_sync(0xffffffffu, mx, 4, 8));
            float nm = fmaxf(mrow[i], mx);
            float corr = ex2(mrow[i] - nm);
            mrow[i] = nm;
            float ss = 0.f;
#pragma unroll
            for (int j = 0; j < 8; j++) { float p = ex2(sv[j] - nm); sv[j] = p; ss += p; }
            ss += __shfl_xor_sync(0xffffffffu, ss, 1, 8);
            ss += __shfl_xor_sync(0xffffffffu, ss, 2, 8);
            ss += __shfl_xor_sync(0xffffffffu, ss, 4, 8);
            lrow[i] = lrow[i] * corr + ss;
            ull c2 = pk2(corr, corr);
#pragma unroll
            for (int j = 0; j < 4; j++) o[i][j] = f2mul(o[i][j], c2);
            float* pr = &Ps[(m0 + i) * PPAD + n0];
            *(float4*)pr       = make_float4(sv[0], sv[1], sv[2], sv[3]);
            *(float4*)(pr + 4) = make_float4(sv[4], sv[5], sv[6], sv[7]);
        }

        // prefetch next K/V tile (hidden under PV)
        if (kt + 1 < nkt) {
            const float* kp = kBase + (size_t)(kt + 1) * 64 * D_;
            const float* vp = vBase + (size_t)(kt + 1) * 64 * D_;
#pragma unroll
            for (int c = 0; c < 4; c++) {
                kv[c] = *(const float4*)(kp + 4*c);
                vv[c] = *(const float4*)(vp + 4*c);
            }
        }
        __syncthreads();                 // Ps complete

        // ---- O += P V  (LDS-fed register GEMM, no shfl) ----
#pragma unroll 8
        for (int k = 0; k < 64; k++) {
            float p0 = Ps[(m0 + 0) * PPAD + k];
            float p1 = Ps[(m0 + 1) * PPAD + k];
            float p2 = Ps[(m0 + 2) * PPAD + k];
            float p3 = Ps[(m0 + 3) * PPAD + k];
            ulonglong2 v01 = *(const ulonglong2*)&Vs[k * VPAD + n0];
            ulonglong2 v23 = *(const ulonglong2*)&Vs[k * VPAD + n0 + 4];
            ull pp0 = pk2(p0, p0), pp1 = pk2(p1, p1);
            ull pp2 = pk2(p2, p2), pp3 = pk2(p3, p3);
            o[0][0] = f2fma(pp0, v01.x, o[0][0]);
            o[0][1] = f2fma(pp0, v01.y, o[0][1]);
            o[0][2] = f2fma(pp0, v23.x, o[0][2]);
            o[0][3] = f2fma(pp0, v23.y, o[0][3]);
            o[1][0] = f2fma(pp1, v01.x, o[1][0]);
            o[1][1] = f2fma(pp1, v01.y, o[1][1]);
            o[1][2] = f2fma(pp1, v23.x, o[1][2]);
            o[1][3] = f2fma(pp1, v23.y, o[1][3]);
            o[2][0] = f2fma(pp2, v01.x, o[2][0]);
            o[2][1] = f2fma(pp2, v01.y, o[2][1]);
            o[2][2] = f2fma(pp2, v23.x, o[2][2]);
            o[2][3] = f2fma(pp2, v23.y, o[2][3]);
            o[3][0] = f2fma(pp3, v01.x, o[3][0]);
            o[3][1] = f2fma(pp3, v01.y, o[3][1]);
            o[3][2] = f2fma(pp3, v23.x, o[3][2]);
            o[3][3] = f2fma(pp3, v23.y, o[3][3]);
        }
    }

#pragma unroll
    for (int i = 0; i < 4; i++) {
        float inv = 1.0f / lrow[i];
        ull iv = pk2(inv, inv);
        float2 a = up2(f2mul(o[i][0], iv)), b2 = up2(f2mul(o[i][1], iv));
        float2 c = up2(f2mul(o[i][2], iv)), d2 = up2(f2mul(o[i][3], iv));
        float* op = Op + headOff + (size_t)(qBase + m0 + i) * D_ + n0;
        *(float4*)op       = make_float4(a.x, a.y, b2.x, b2.y);
        *(float4*)(op + 4) = make_float4(c.x, c.y, d2.x, d2.y);
    }
}

// Tiny no-op: shifts launch parity so ncu (-s 5 -c 1) captures flash_v3b
// (sequence per call: gemm, flash, dummy, gemm -> 6th launch = flash).
__global__ void parity_pad_kernel() {}

// ---------------------------------------------------------------------------
extern "C" void kernel_launch(void* const* d_in, const int* in_sizes, int n_in,
                              void* d_out, int out_size)
{
    const float* Q  = (const float*)d_in[0];
    const float* Kx = (const float*)d_in[1];
    const float* Vx = (const float*)d_in[2];
    const float* Wq = (const float*)d_in[3];
    const float* Wk = (const float*)d_in[4];
    const float* Wv = (const float*)d_in[5];
    const float* Wo = (const float*)d_in[6];
    float* out = (float*)d_out;

    float *q, *k, *v, *o;
    cudaGetSymbolAddress((void**)&q, g_q);
    cudaGetSymbolAddress((void**)&k, g_k);
    cudaGetSymbolAddress((void**)&v, g_v);
    cudaGetSymbolAddress((void**)&o, g_o);

    const int flashSmem =
        (64 * 128 + 64 * 64 + 64 * VPAD + 128 * PPAD) * sizeof(float); // 101632
    cudaFuncSetAttribute(flash_v3b, cudaFuncAttributeMaxDynamicSharedMemorySize, flashSmem);

    gemm128<<<dim3(8, 64, 3), 256>>>(Q, Kx, Vx, Wq, Wk, Wv, q, k, v);
    flash_v3b<<<dim3(S_ / 128, B_ * H_), 256, flashSmem>>>(q, k, v, o);
    parity_pad_kernel<<<1, 1>>>();
    gemm128<<<dim3(8, 64, 1), 256>>>(o, o, o, Wo, Wo, Wo, out, out, out);
}